// round 2
// baseline (speedup 1.0000x reference)
#include <cuda_runtime.h>
#include <cuda_bf16.h>

#define B_SZ   8
#define T_SZ   2048
#define VOCAB  8192
#define NT     1024

__global__ __launch_bounds__(NT)
void constrained_attn_kernel(const int* __restrict__ x,
                             const float* __restrict__ params,
                             float* __restrict__ out)
{
    __shared__ short toks[T_SZ];      // 4 KB
    __shared__ float scores[T_SZ];    // 8 KB
    __shared__ float vocab[VOCAB];    // 32 KB
    __shared__ float red[32];

    const int b   = blockIdx.x;
    const int tid = threadIdx.x;
    const int lane = tid & 31;
    const int warp = tid >> 5;

    const int* xb = x + b * T_SZ;

    // Load tokens (fit in int16 since VOCAB=8192) and zero vocab accumulator.
    #pragma unroll
    for (int t = tid; t < T_SZ; t += NT) toks[t] = (short)xb[t];
    #pragma unroll
    for (int v = tid; v < VOCAB; v += NT) vocab[v] = 0.0f;
    __syncthreads();

    // Query tokens: q[i] = x[b, T-1-i]
    const int q0 = toks[T_SZ - 1];
    const int q1 = toks[T_SZ - 2];
    const int q2 = toks[T_SZ - 3];

    // params[i][j], i = query offset, j = key offset
    float p[3][3];
    #pragma unroll
    for (int i = 0; i < 3; i++)
        #pragma unroll
        for (int j = 0; j < 3; j++)
            p[i][j] = params[i * 3 + j];

    // ---- scores + local max ----
    float lmax = -1e30f;
    #pragma unroll
    for (int t = tid; t < T_SZ; t += NT) {
        float s;
        if (t == T_SZ - 1) {
            s = -1000000000.0f;
        } else {
            const int k0 = toks[t];
            const int k1 = (t >= 1) ? (int)toks[t - 1] : -1;  // -1 never matches
            const int k2 = (t >= 2) ? (int)toks[t - 2] : -1;
            s  = (q0 == k0) ? p[0][0] : 0.0f;
            s += (q0 == k1) ? p[0][1] : 0.0f;
            s += (q0 == k2) ? p[0][2] : 0.0f;
            s += (q1 == k0) ? p[1][0] : 0.0f;
            s += (q1 == k1) ? p[1][1] : 0.0f;
            s += (q1 == k2) ? p[1][2] : 0.0f;
            s += (q2 == k0) ? p[2][0] : 0.0f;
            s += (q2 == k1) ? p[2][1] : 0.0f;
            s += (q2 == k2) ? p[2][2] : 0.0f;
        }
        scores[t] = s;
        lmax = fmaxf(lmax, s);
    }

    // ---- block max reduction ----
    #pragma unroll
    for (int off = 16; off; off >>= 1)
        lmax = fmaxf(lmax, __shfl_xor_sync(0xffffffffu, lmax, off));
    if (lane == 0) red[warp] = lmax;
    __syncthreads();
    if (warp == 0) {
        float v = red[lane];
        #pragma unroll
        for (int off = 16; off; off >>= 1)
            v = fmaxf(v, __shfl_xor_sync(0xffffffffu, v, off));
        if (lane == 0) red[0] = v;
    }
    __syncthreads();
    const float gmax = red[0];
    __syncthreads();   // protect red[] before reuse for sum

    // ---- exp + local sum ----
    float lsum = 0.0f;
    #pragma unroll
    for (int t = tid; t < T_SZ; t += NT) {
        const float e = expf(scores[t] - gmax);
        scores[t] = e;
        lsum += e;
    }

    // ---- block sum reduction ----
    #pragma unroll
    for (int off = 16; off; off >>= 1)
        lsum += __shfl_xor_sync(0xffffffffu, lsum, off);
    if (lane == 0) red[warp] = lsum;
    __syncthreads();
    if (warp == 0) {
        float v = red[lane];
        #pragma unroll
        for (int off = 16; off; off >>= 1)
            v += __shfl_xor_sync(0xffffffffu, v, off);
        if (lane == 0) red[0] = v;
    }
    __syncthreads();
    const float inv = 1.0f / red[0];

    // ---- scatter attn into shared vocab histogram ----
    #pragma unroll
    for (int t = tid; t < T_SZ; t += NT)
        atomicAdd(&vocab[(int)toks[t]], scores[t] * inv);
    __syncthreads();

    // ---- write out ----
    float* ob = out + b * VOCAB;
    #pragma unroll
    for (int v = tid; v < VOCAB; v += NT)
        ob[v] = vocab[v];
}

extern "C" void kernel_launch(void* const* d_in, const int* in_sizes, int n_in,
                              void* d_out, int out_size)
{
    const int*   x      = (const int*)d_in[0];     // (8, 2048) int32
    const float* params = (const float*)d_in[1];   // (3, 3) float32
    float*       out    = (float*)d_out;           // (8, 8192) float32

    (void)in_sizes; (void)n_in; (void)out_size;
    constrained_attn_kernel<<<B_SZ, NT>>>(x, params, out);
}